// round 1
// baseline (speedup 1.0000x reference)
#include <cuda_runtime.h>
#include <math.h>

// Shapes (fixed by the problem)
#define Bz     4
#define Tt     2048
#define Dm     1024          // d_model = K-dim of all GEMMs; also N of all GEMMs
#define Hh     16
#define Dh     64
#define Mrows  (Bz * Tt)     // 8192

// ---- scratch (no cudaMalloc allowed) ----
__device__ float g_Q[Mrows * Dm];
__device__ float g_K[Mrows * Dm];
__device__ float g_V[Mrows * Dm];
__device__ float g_ctx[Mrows * Dm];

// ======================= SGEMM 128x128x8, 8x8 microtile =======================
// C[M,N] = A[M,K] * B[K,N], all row-major, M=8192, N=K=1024 (multiples of tiles)
__device__ __forceinline__ void sgemm_body(const float* __restrict__ A,
                                           const float* __restrict__ B,
                                           float* __restrict__ C)
{
    __shared__ float As[8][128];   // transposed A tile
    __shared__ float Bs[8][128];

    const int tid = threadIdx.x;           // 0..255
    const int tx  = tid & 15;              // 0..15 (N dir)
    const int ty  = tid >> 4;              // 0..15 (M dir)

    const int aRow = tid >> 1;             // 0..127
    const int aCol = (tid & 1) * 4;        // 0 or 4
    const int bRow = tid >> 5;             // 0..7
    const int bCol = (tid & 31) * 4;       // 0..124

    const float* Ablk = A + (size_t)(blockIdx.y * 128) * Dm;
    const float* Bblk = B + blockIdx.x * 128;

    float acc[8][8];
    #pragma unroll
    for (int i = 0; i < 8; i++)
        #pragma unroll
        for (int j = 0; j < 8; j++) acc[i][j] = 0.f;

    for (int k0 = 0; k0 < Dm; k0 += 8) {
        float4 a4 = *(const float4*)(Ablk + (size_t)aRow * Dm + k0 + aCol);
        As[aCol + 0][aRow] = a4.x;
        As[aCol + 1][aRow] = a4.y;
        As[aCol + 2][aRow] = a4.z;
        As[aCol + 3][aRow] = a4.w;
        *(float4*)&Bs[bRow][bCol] =
            *(const float4*)(Bblk + (size_t)(k0 + bRow) * Dm + bCol);
        __syncthreads();

        #pragma unroll
        for (int k = 0; k < 8; k++) {
            float ar[8], br[8];
            #pragma unroll
            for (int i = 0; i < 8; i++) ar[i] = As[k][ty * 8 + i];
            #pragma unroll
            for (int j = 0; j < 8; j++) br[j] = Bs[k][tx * 8 + j];
            #pragma unroll
            for (int i = 0; i < 8; i++)
                #pragma unroll
                for (int j = 0; j < 8; j++)
                    acc[i][j] += ar[i] * br[j];
        }
        __syncthreads();
    }

    float* Cblk = C + (size_t)(blockIdx.y * 128) * Dm + blockIdx.x * 128;
    #pragma unroll
    for (int i = 0; i < 8; i++) {
        float4 v0 = make_float4(acc[i][0], acc[i][1], acc[i][2], acc[i][3]);
        float4 v1 = make_float4(acc[i][4], acc[i][5], acc[i][6], acc[i][7]);
        *(float4*)&Cblk[(size_t)(ty * 8 + i) * Dm + tx * 8]     = v0;
        *(float4*)&Cblk[(size_t)(ty * 8 + i) * Dm + tx * 8 + 4] = v1;
    }
}

__global__ __launch_bounds__(256) void gemm_qkv(const float* __restrict__ x,
                                                const float* __restrict__ Wq,
                                                const float* __restrict__ Wk,
                                                const float* __restrict__ Wv)
{
    const float* W = (blockIdx.z == 0) ? Wq : (blockIdx.z == 1) ? Wk : Wv;
    float*       C = (blockIdx.z == 0) ? g_Q : (blockIdx.z == 1) ? g_K : g_V;
    sgemm_body(x, W, C);
}

__global__ __launch_bounds__(256) void gemm_out(const float* __restrict__ Wo,
                                                float* __restrict__ out)
{
    sgemm_body(g_ctx, Wo, out);
}

// ======================= causal flash attention =======================
// grid: (T/128, H, B); block 128 threads; thread t handles query row blockIdx.x*128+t
__global__ __launch_bounds__(128) void attn_kernel()
{
    __shared__ float Ks[64 * 64];
    __shared__ float Vs[64 * 64];

    const int tid = threadIdx.x;
    const int b = blockIdx.z, h = blockIdx.y;
    const int r = blockIdx.x * 128 + tid;   // query index in T
    const float scale = 0.125f;             // 1/sqrt(64)

    const float* Qrow = g_Q + ((size_t)(b * Tt + r)) * Dm + h * Dh;
    float q[64];
    #pragma unroll
    for (int d = 0; d < 64; d += 4) {
        float4 v = *(const float4*)(Qrow + d);
        q[d] = v.x; q[d+1] = v.y; q[d+2] = v.z; q[d+3] = v.w;
    }

    float m = -INFINITY, l = 0.f;
    float acc[64];
    #pragma unroll
    for (int d = 0; d < 64; d++) acc[d] = 0.f;

    const int ntiles = 2 * blockIdx.x + 2;   // key tiles of 64 covering rows <= block max
    for (int kt = 0; kt < ntiles; kt++) {
        const size_t base = ((size_t)(b * Tt + kt * 64)) * Dm + h * Dh;
        #pragma unroll
        for (int i = 0; i < 8; i++) {
            int idx = tid + i * 128;        // float4 index 0..1023
            int row = idx >> 4;
            int c4  = (idx & 15) * 4;
            *(float4*)&Ks[row * 64 + c4] = *(const float4*)(g_K + base + (size_t)row * Dm + c4);
            *(float4*)&Vs[row * 64 + c4] = *(const float4*)(g_V + base + (size_t)row * Dm + c4);
        }
        __syncthreads();

        int jmax = r - kt * 64;                       // keys valid while j <= jmax
        int jend = (jmax >= 63) ? 64 : (jmax + 1);
        if (jend < 0) jend = 0;

        for (int j = 0; j < jend; j++) {
            const float* kr = &Ks[j * 64];
            float s0 = 0.f, s1 = 0.f, s2 = 0.f, s3 = 0.f;
            #pragma unroll
            for (int d = 0; d < 64; d += 4) {
                s0 += q[d]     * kr[d];
                s1 += q[d + 1] * kr[d + 1];
                s2 += q[d + 2] * kr[d + 2];
                s3 += q[d + 3] * kr[d + 3];
            }
            float s = (s0 + s1 + s2 + s3) * scale;

            if (s > m) {                           // online-softmax rescale (rare)
                float corr = __expf(m - s);
                m = s;
                l *= corr;
                #pragma unroll
                for (int d = 0; d < 64; d++) acc[d] *= corr;
            }
            float p = __expf(s - m);
            l += p;
            const float* vr = &Vs[j * 64];
            #pragma unroll
            for (int d = 0; d < 64; d++) acc[d] += p * vr[d];
        }
        __syncthreads();
    }

    float inv = 1.f / l;
    float* orow = g_ctx + ((size_t)(b * Tt + r)) * Dm + h * Dh;
    #pragma unroll
    for (int d = 0; d < 64; d += 4) {
        float4 v = make_float4(acc[d] * inv, acc[d+1] * inv, acc[d+2] * inv, acc[d+3] * inv);
        *(float4*)(orow + d) = v;
    }
}

// ======================= launch =======================
extern "C" void kernel_launch(void* const* d_in, const int* in_sizes, int n_in,
                              void* d_out, int out_size)
{
    const float* x  = (const float*)d_in[0];
    const float* Wq = (const float*)d_in[1];
    const float* Wk = (const float*)d_in[2];
    const float* Wv = (const float*)d_in[3];
    const float* Wo = (const float*)d_in[4];
    float* out = (float*)d_out;

    dim3 gQKV(Dm / 128, Mrows / 128, 3);
    gemm_qkv<<<gQKV, 256>>>(x, Wq, Wk, Wv);

    dim3 gA(Tt / 128, Hh, Bz);
    attn_kernel<<<gA, 128>>>();

    dim3 gO(Dm / 128, Mrows / 128, 1);
    gemm_out<<<gO, 256>>>(Wo, out);
}

// round 2
// speedup vs baseline: 1.5149x; 1.5149x over previous
#include <cuda_runtime.h>
#include <math.h>
#include <stdint.h>

// Shapes (fixed by the problem)
#define Bz     4
#define Tt     2048
#define Dm     1024
#define Hh     16
#define Dh     64
#define Mrows  (Bz * Tt)     // 8192

// ---- scratch (no cudaMalloc allowed) ----
__device__ float g_Q[Mrows * Dm];
__device__ float g_K[Mrows * Dm];
__device__ float g_V[Mrows * Dm];
__device__ float g_ctx[Mrows * Dm];

__device__ __forceinline__ uint32_t f2tf32(float x) {
    uint32_t r;
    asm("cvt.rna.tf32.f32 %0, %1;" : "=r"(r) : "f"(x));
    return r;
}

// ================== tf32 tensor-core GEMM: C[M,N] = A[M,K] * B[K,N] ==================
// Block tile 128x128, BK=32, 256 threads = 8 warps (4x2), warp tile 32x64.
// Each warp: 2 m16 tiles x 8 n8 tiles of mma.m16n8k8.tf32.
#define BM 128
#define BN 128
#define BK 32
#define AS_STRIDE 36   // banks (4r + c) mod 32 distinct -> conflict-free A frag loads
#define BS_STRIDE 136  // banks (8k + n) mod 32 distinct -> conflict-free B frag loads

__device__ __forceinline__ void gemm_tf32_body(const float* __restrict__ A,
                                               const float* __restrict__ B,
                                               float* __restrict__ C)
{
    __shared__ uint32_t As[BM * AS_STRIDE];
    __shared__ uint32_t Bs[BK * BS_STRIDE];

    const int tid  = threadIdx.x;
    const int lane = tid & 31;
    const int warp = tid >> 5;
    const int wm   = warp >> 1;   // 0..3
    const int wn   = warp & 1;    // 0..1

    const int bM = blockIdx.y * BM;
    const int bN = blockIdx.x * BN;

    const int ar = lane >> 2;     // groupID 0..7
    const int ac = lane & 3;      // threadID_in_group 0..3

    float acc[2][8][4];
    #pragma unroll
    for (int mt = 0; mt < 2; mt++)
        #pragma unroll
        for (int nt = 0; nt < 8; nt++)
            #pragma unroll
            for (int i = 0; i < 4; i++) acc[mt][nt][i] = 0.f;

    for (int k0 = 0; k0 < Dm; k0 += BK) {
        // ---- stage A tile (128x32) as tf32, coalesced float4 loads ----
        #pragma unroll
        for (int i = 0; i < 4; i++) {
            int f   = tid + i * 256;       // float4 index, 1024 total
            int row = f >> 3;              // 8 float4 per row
            int c4  = (f & 7) * 4;
            float4 v = *(const float4*)(A + (size_t)(bM + row) * Dm + k0 + c4);
            uint32_t* dst = &As[row * AS_STRIDE + c4];
            dst[0] = f2tf32(v.x); dst[1] = f2tf32(v.y);
            dst[2] = f2tf32(v.z); dst[3] = f2tf32(v.w);
        }
        // ---- stage B tile (32x128) as tf32 ----
        #pragma unroll
        for (int i = 0; i < 4; i++) {
            int f   = tid + i * 256;
            int row = f >> 5;              // 32 float4 per row
            int c4  = (f & 31) * 4;
            float4 v = *(const float4*)(B + (size_t)(k0 + row) * Dm + bN + c4);
            uint32_t* dst = &Bs[row * BS_STRIDE + c4];
            dst[0] = f2tf32(v.x); dst[1] = f2tf32(v.y);
            dst[2] = f2tf32(v.z); dst[3] = f2tf32(v.w);
        }
        __syncthreads();

        #pragma unroll
        for (int k8 = 0; k8 < BK / 8; k8++) {
            const int k = k8 * 8;
            uint32_t afrag[2][4];
            #pragma unroll
            for (int mt = 0; mt < 2; mt++) {
                const int mo = wm * 32 + mt * 16;
                afrag[mt][0] = As[(mo + ar    ) * AS_STRIDE + k + ac];
                afrag[mt][1] = As[(mo + ar + 8) * AS_STRIDE + k + ac];
                afrag[mt][2] = As[(mo + ar    ) * AS_STRIDE + k + ac + 4];
                afrag[mt][3] = As[(mo + ar + 8) * AS_STRIDE + k + ac + 4];
            }
            #pragma unroll
            for (int nt = 0; nt < 8; nt++) {
                const int no = wn * 64 + nt * 8;
                uint32_t b0 = Bs[(k + ac    ) * BS_STRIDE + no + ar];
                uint32_t b1 = Bs[(k + ac + 4) * BS_STRIDE + no + ar];
                #pragma unroll
                for (int mt = 0; mt < 2; mt++) {
                    asm volatile(
                        "mma.sync.aligned.m16n8k8.row.col.f32.tf32.tf32.f32 "
                        "{%0,%1,%2,%3}, {%4,%5,%6,%7}, {%8,%9}, {%0,%1,%2,%3};\n"
                        : "+f"(acc[mt][nt][0]), "+f"(acc[mt][nt][1]),
                          "+f"(acc[mt][nt][2]), "+f"(acc[mt][nt][3])
                        : "r"(afrag[mt][0]), "r"(afrag[mt][1]),
                          "r"(afrag[mt][2]), "r"(afrag[mt][3]),
                          "r"(b0), "r"(b1));
                }
            }
        }
        __syncthreads();
    }

    // ---- epilogue ----
    #pragma unroll
    for (int mt = 0; mt < 2; mt++) {
        const int row0 = bM + wm * 32 + mt * 16 + ar;
        #pragma unroll
        for (int nt = 0; nt < 8; nt++) {
            const int col = bN + wn * 64 + nt * 8 + ac * 2;
            *(float2*)(C + (size_t)row0 * Dm + col)       = make_float2(acc[mt][nt][0], acc[mt][nt][1]);
            *(float2*)(C + (size_t)(row0 + 8) * Dm + col) = make_float2(acc[mt][nt][2], acc[mt][nt][3]);
        }
    }
}

__global__ __launch_bounds__(256) void gemm_qkv(const float* __restrict__ x,
                                                const float* __restrict__ Wq,
                                                const float* __restrict__ Wk,
                                                const float* __restrict__ Wv)
{
    const float* W = (blockIdx.z == 0) ? Wq : (blockIdx.z == 1) ? Wk : Wv;
    float*       C = (blockIdx.z == 0) ? g_Q : (blockIdx.z == 1) ? g_K : g_V;
    gemm_tf32_body(x, W, C);
}

__global__ __launch_bounds__(256) void gemm_out(const float* __restrict__ Wo,
                                                float* __restrict__ out)
{
    gemm_tf32_body(g_ctx, Wo, out);
}

// ======================= causal flash attention (fp32 SIMT, unchanged) =======================
__global__ __launch_bounds__(128) void attn_kernel()
{
    __shared__ float Ks[64 * 64];
    __shared__ float Vs[64 * 64];

    const int tid = threadIdx.x;
    const int b = blockIdx.z, h = blockIdx.y;
    const int r = blockIdx.x * 128 + tid;
    const float scale = 0.125f;

    const float* Qrow = g_Q + ((size_t)(b * Tt + r)) * Dm + h * Dh;
    float q[64];
    #pragma unroll
    for (int d = 0; d < 64; d += 4) {
        float4 v = *(const float4*)(Qrow + d);
        q[d] = v.x; q[d+1] = v.y; q[d+2] = v.z; q[d+3] = v.w;
    }

    float m = -INFINITY, l = 0.f;
    float acc[64];
    #pragma unroll
    for (int d = 0; d < 64; d++) acc[d] = 0.f;

    const int ntiles = 2 * blockIdx.x + 2;
    for (int kt = 0; kt < ntiles; kt++) {
        const size_t base = ((size_t)(b * Tt + kt * 64)) * Dm + h * Dh;
        #pragma unroll
        for (int i = 0; i < 8; i++) {
            int idx = tid + i * 128;
            int row = idx >> 4;
            int c4  = (idx & 15) * 4;
            *(float4*)&Ks[row * 64 + c4] = *(const float4*)(g_K + base + (size_t)row * Dm + c4);
            *(float4*)&Vs[row * 64 + c4] = *(const float4*)(g_V + base + (size_t)row * Dm + c4);
        }
        __syncthreads();

        int jmax = r - kt * 64;
        int jend = (jmax >= 63) ? 64 : (jmax + 1);
        if (jend < 0) jend = 0;

        for (int j = 0; j < jend; j++) {
            const float* kr = &Ks[j * 64];
            float s0 = 0.f, s1 = 0.f, s2 = 0.f, s3 = 0.f;
            #pragma unroll
            for (int d = 0; d < 64; d += 4) {
                s0 += q[d]     * kr[d];
                s1 += q[d + 1] * kr[d + 1];
                s2 += q[d + 2] * kr[d + 2];
                s3 += q[d + 3] * kr[d + 3];
            }
            float s = (s0 + s1 + s2 + s3) * scale;

            if (s > m) {
                float corr = __expf(m - s);
                m = s;
                l *= corr;
                #pragma unroll
                for (int d = 0; d < 64; d++) acc[d] *= corr;
            }
            float p = __expf(s - m);
            l += p;
            const float* vr = &Vs[j * 64];
            #pragma unroll
            for (int d = 0; d < 64; d++) acc[d] += p * vr[d];
        }
        __syncthreads();
    }

    float inv = 1.f / l;
    float* orow = g_ctx + ((size_t)(b * Tt + r)) * Dm + h * Dh;
    #pragma unroll
    for (int d = 0; d < 64; d += 4) {
        float4 v = make_float4(acc[d] * inv, acc[d+1] * inv, acc[d+2] * inv, acc[d+3] * inv);
        *(float4*)(orow + d) = v;
    }
}

// ======================= launch =======================
extern "C" void kernel_launch(void* const* d_in, const int* in_sizes, int n_in,
                              void* d_out, int out_size)
{
    const float* x  = (const float*)d_in[0];
    const float* Wq = (const float*)d_in[1];
    const float* Wk = (const float*)d_in[2];
    const float* Wv = (const float*)d_in[3];
    const float* Wo = (const float*)d_in[4];
    float* out = (float*)d_out;

    dim3 gQKV(Dm / BN, Mrows / BM, 3);
    gemm_qkv<<<gQKV, 256>>>(x, Wq, Wk, Wv);

    dim3 gA(Tt / 128, Hh, Bz);
    attn_kernel<<<gA, 128>>>();

    dim3 gO(Dm / BN, Mrows / BM, 1);
    gemm_out<<<gO, 256>>>(Wo, out);
}

// round 4
// speedup vs baseline: 4.2328x; 2.7942x over previous
#include <cuda_runtime.h>
#include <math.h>
#include <stdint.h>

// Shapes (fixed by the problem)
#define Bz     4
#define Tt     2048
#define Dm     1024
#define Hh     16
#define Dh     64
#define Mrows  (Bz * Tt)     // 8192

// ---- scratch (no cudaMalloc allowed) ----
__device__ float g_Q[Mrows * Dm];
__device__ float g_K[Mrows * Dm];
__device__ float g_V[Mrows * Dm];
__device__ float g_ctx[Mrows * Dm];

__device__ __forceinline__ uint32_t f2tf32(float x) {
    uint32_t r;
    asm("cvt.rna.tf32.f32 %0, %1;" : "=r"(r) : "f"(x));
    return r;
}

// ================== tf32 tensor-core GEMM: C[M,N] = A[M,K] * B[K,N] ==================
#define BM 128
#define BN 128
#define BK 32
#define AS_STRIDE 36
#define BS_STRIDE 136

__device__ __forceinline__ void gemm_tf32_body(const float* __restrict__ A,
                                               const float* __restrict__ B,
                                               float* __restrict__ C)
{
    __shared__ uint32_t As[BM * AS_STRIDE];
    __shared__ uint32_t Bs[BK * BS_STRIDE];

    const int tid  = threadIdx.x;
    const int lane = tid & 31;
    const int warp = tid >> 5;
    const int wm   = warp >> 1;
    const int wn   = warp & 1;

    const int bM = blockIdx.y * BM;
    const int bN = blockIdx.x * BN;

    const int ar = lane >> 2;
    const int ac = lane & 3;

    float acc[2][8][4];
    #pragma unroll
    for (int mt = 0; mt < 2; mt++)
        #pragma unroll
        for (int nt = 0; nt < 8; nt++)
            #pragma unroll
            for (int i = 0; i < 4; i++) acc[mt][nt][i] = 0.f;

    for (int k0 = 0; k0 < Dm; k0 += BK) {
        #pragma unroll
        for (int i = 0; i < 4; i++) {
            int f   = tid + i * 256;
            int row = f >> 3;
            int c4  = (f & 7) * 4;
            float4 v = *(const float4*)(A + (size_t)(bM + row) * Dm + k0 + c4);
            uint32_t* dst = &As[row * AS_STRIDE + c4];
            dst[0] = f2tf32(v.x); dst[1] = f2tf32(v.y);
            dst[2] = f2tf32(v.z); dst[3] = f2tf32(v.w);
        }
        #pragma unroll
        for (int i = 0; i < 4; i++) {
            int f   = tid + i * 256;
            int row = f >> 5;
            int c4  = (f & 31) * 4;
            float4 v = *(const float4*)(B + (size_t)(k0 + row) * Dm + bN + c4);
            uint32_t* dst = &Bs[row * BS_STRIDE + c4];
            dst[0] = f2tf32(v.x); dst[1] = f2tf32(v.y);
            dst[2] = f2tf32(v.z); dst[3] = f2tf32(v.w);
        }
        __syncthreads();

        #pragma unroll
        for (int k8 = 0; k8 < BK / 8; k8++) {
            const int k = k8 * 8;
            uint32_t afrag[2][4];
            #pragma unroll
            for (int mt = 0; mt < 2; mt++) {
                const int mo = wm * 32 + mt * 16;
                afrag[mt][0] = As[(mo + ar    ) * AS_STRIDE + k + ac];
                afrag[mt][1] = As[(mo + ar + 8) * AS_STRIDE + k + ac];
                afrag[mt][2] = As[(mo + ar    ) * AS_STRIDE + k + ac + 4];
                afrag[mt][3] = As[(mo + ar + 8) * AS_STRIDE + k + ac + 4];
            }
            #pragma unroll
            for (int nt = 0; nt < 8; nt++) {
                const int no = wn * 64 + nt * 8;
                uint32_t b0 = Bs[(k + ac    ) * BS_STRIDE + no + ar];
                uint32_t b1 = Bs[(k + ac + 4) * BS_STRIDE + no + ar];
                #pragma unroll
                for (int mt = 0; mt < 2; mt++) {
                    asm volatile(
                        "mma.sync.aligned.m16n8k8.row.col.f32.tf32.tf32.f32 "
                        "{%0,%1,%2,%3}, {%4,%5,%6,%7}, {%8,%9}, {%0,%1,%2,%3};\n"
                        : "+f"(acc[mt][nt][0]), "+f"(acc[mt][nt][1]),
                          "+f"(acc[mt][nt][2]), "+f"(acc[mt][nt][3])
                        : "r"(afrag[mt][0]), "r"(afrag[mt][1]),
                          "r"(afrag[mt][2]), "r"(afrag[mt][3]),
                          "r"(b0), "r"(b1));
                }
            }
        }
        __syncthreads();
    }

    #pragma unroll
    for (int mt = 0; mt < 2; mt++) {
        const int row0 = bM + wm * 32 + mt * 16 + ar;
        #pragma unroll
        for (int nt = 0; nt < 8; nt++) {
            const int col = bN + wn * 64 + nt * 8 + ac * 2;
            *(float2*)(C + (size_t)row0 * Dm + col)       = make_float2(acc[mt][nt][0], acc[mt][nt][1]);
            *(float2*)(C + (size_t)(row0 + 8) * Dm + col) = make_float2(acc[mt][nt][2], acc[mt][nt][3]);
        }
    }
}

__global__ __launch_bounds__(256) void gemm_qkv(const float* __restrict__ x,
                                                const float* __restrict__ Wq,
                                                const float* __restrict__ Wk,
                                                const float* __restrict__ Wv)
{
    const float* W = (blockIdx.z == 0) ? Wq : (blockIdx.z == 1) ? Wk : Wv;
    float*       C = (blockIdx.z == 0) ? g_Q : (blockIdx.z == 1) ? g_K : g_V;
    gemm_tf32_body(x, W, C);
}

__global__ __launch_bounds__(256) void gemm_out(const float* __restrict__ Wo,
                                                float* __restrict__ out)
{
    gemm_tf32_body(g_ctx, Wo, out);
}

// ======================= tensor-core causal flash attention =======================
// Block: 128 threads (4 warps), 128 query rows (warp w owns rows w*32..w*32+31, 2 m16 tiles).
// Key tiles of 64. S = QK^T and PV both via mma.m16n8k8.tf32.
#define QS 68   // Qs stride (words): frag banks (4*ar + ac + k) distinct
#define KS 68   // Ks stride
#define VS 72   // Vs stride: B-frag banks (8*ac + ar) distinct
#define PS 68   // P buffer stride

#define ATTN_SMEM_WORDS (128*QS + 64*KS + 64*VS + 4*32*PS)
#define ATTN_SMEM_BYTES (ATTN_SMEM_WORDS * 4)

__global__ __launch_bounds__(128) void attn_mma()
{
    extern __shared__ uint32_t smw[];
    uint32_t* Qs  = smw;                 // 128 x QS
    uint32_t* Ksm = Qs  + 128 * QS;      // 64 x KS
    uint32_t* Vsm = Ksm + 64 * KS;       // 64 x VS
    uint32_t* Psm = Vsm + 64 * VS;       // 4 warps x 32 x PS

    const int tid  = threadIdx.x;
    const int lane = tid & 31;
    const int warp = tid >> 5;
    const int ar   = lane >> 2;
    const int ac   = lane & 3;

    const int qt = blockIdx.x, h = blockIdx.y, b = blockIdx.z;
    const int q0 = qt * 128;

    // ---- stage Q tile (scale 1/8 folded in) ----
    const float* Qg = g_Q + ((size_t)(b * Tt + q0)) * Dm + h * Dh;
    #pragma unroll
    for (int i = 0; i < 16; i++) {
        int f = tid + i * 128;
        int row = f >> 4;
        int c4  = (f & 15) * 4;
        float4 v = *(const float4*)(Qg + (size_t)row * Dm + c4);
        uint32_t* d = &Qs[row * QS + c4];
        d[0] = f2tf32(v.x * 0.125f); d[1] = f2tf32(v.y * 0.125f);
        d[2] = f2tf32(v.z * 0.125f); d[3] = f2tf32(v.w * 0.125f);
    }

    float accO[2][8][4];
    #pragma unroll
    for (int mt = 0; mt < 2; mt++)
        #pragma unroll
        for (int nt = 0; nt < 8; nt++)
            #pragma unroll
            for (int i = 0; i < 4; i++) accO[mt][nt][i] = 0.f;

    float mrow[2][2], lrow[2][2];
    #pragma unroll
    for (int mt = 0; mt < 2; mt++) {
        mrow[mt][0] = mrow[mt][1] = -1e30f;
        lrow[mt][0] = lrow[mt][1] = 0.f;
    }

    uint32_t* Pw = Psm + warp * 32 * PS;
    const int ntiles = 2 * qt + 2;

    for (int kt = 0; kt < ntiles; kt++) {
        // ---- stage K/V tile (64 x 64) as tf32 ----
        const size_t kvbase = ((size_t)(b * Tt + kt * 64)) * Dm + h * Dh;
        __syncthreads();   // protect previous tile's Ksm/Vsm reads
        #pragma unroll
        for (int i = 0; i < 8; i++) {
            int f = tid + i * 128;
            int row = f >> 4;
            int c4  = (f & 15) * 4;
            float4 kv = *(const float4*)(g_K + kvbase + (size_t)row * Dm + c4);
            uint32_t* dk = &Ksm[row * KS + c4];
            dk[0] = f2tf32(kv.x); dk[1] = f2tf32(kv.y);
            dk[2] = f2tf32(kv.z); dk[3] = f2tf32(kv.w);
            float4 vv = *(const float4*)(g_V + kvbase + (size_t)row * Dm + c4);
            uint32_t* dv = &Vsm[row * VS + c4];
            dv[0] = f2tf32(vv.x); dv[1] = f2tf32(vv.y);
            dv[2] = f2tf32(vv.z); dv[3] = f2tf32(vv.w);
        }
        __syncthreads();

        // ---- S = Q K^T  (per warp: 32 x 64) ----
        float s[2][8][4];
        #pragma unroll
        for (int mt = 0; mt < 2; mt++)
            #pragma unroll
            for (int nt = 0; nt < 8; nt++)
                #pragma unroll
                for (int i = 0; i < 4; i++) s[mt][nt][i] = 0.f;

        #pragma unroll
        for (int k8 = 0; k8 < 8; k8++) {
            const int k = k8 * 8;
            uint32_t a[2][4];
            #pragma unroll
            for (int mt = 0; mt < 2; mt++) {
                const int mo = warp * 32 + mt * 16;
                a[mt][0] = Qs[(mo + ar    ) * QS + k + ac];
                a[mt][1] = Qs[(mo + ar + 8) * QS + k + ac];
                a[mt][2] = Qs[(mo + ar    ) * QS + k + ac + 4];
                a[mt][3] = Qs[(mo + ar + 8) * QS + k + ac + 4];
            }
            #pragma unroll
            for (int nt = 0; nt < 8; nt++) {
                const int n = nt * 8;
                uint32_t b0 = Ksm[(n + ar) * KS + k + ac];
                uint32_t b1 = Ksm[(n + ar) * KS + k + ac + 4];
                #pragma unroll
                for (int mt = 0; mt < 2; mt++) {
                    asm volatile(
                        "mma.sync.aligned.m16n8k8.row.col.f32.tf32.tf32.f32 "
                        "{%0,%1,%2,%3}, {%4,%5,%6,%7}, {%8,%9}, {%0,%1,%2,%3};\n"
                        : "+f"(s[mt][nt][0]), "+f"(s[mt][nt][1]),
                          "+f"(s[mt][nt][2]), "+f"(s[mt][nt][3])
                        : "r"(a[mt][0]), "r"(a[mt][1]), "r"(a[mt][2]), "r"(a[mt][3]),
                          "r"(b0), "r"(b1));
                }
            }
        }

        // ---- causal mask (edge tiles only) + online softmax ----
        const bool need_mask = (kt >= 2 * qt);
        #pragma unroll
        for (int mt = 0; mt < 2; mt++) {
            const int r0 = q0 + warp * 32 + mt * 16 + ar;   // rows r0 and r0+8
            if (need_mask) {
                #pragma unroll
                for (int nt = 0; nt < 8; nt++) {
                    const int c0 = kt * 64 + nt * 8 + 2 * ac;
                    if (c0     > r0    ) s[mt][nt][0] = -1e30f;
                    if (c0 + 1 > r0    ) s[mt][nt][1] = -1e30f;
                    if (c0     > r0 + 8) s[mt][nt][2] = -1e30f;
                    if (c0 + 1 > r0 + 8) s[mt][nt][3] = -1e30f;
                }
            }
            float mx0 = -1e30f, mx1 = -1e30f;
            #pragma unroll
            for (int nt = 0; nt < 8; nt++) {
                mx0 = fmaxf(mx0, fmaxf(s[mt][nt][0], s[mt][nt][1]));
                mx1 = fmaxf(mx1, fmaxf(s[mt][nt][2], s[mt][nt][3]));
            }
            mx0 = fmaxf(mx0, __shfl_xor_sync(0xffffffff, mx0, 1));
            mx0 = fmaxf(mx0, __shfl_xor_sync(0xffffffff, mx0, 2));
            mx1 = fmaxf(mx1, __shfl_xor_sync(0xffffffff, mx1, 1));
            mx1 = fmaxf(mx1, __shfl_xor_sync(0xffffffff, mx1, 2));

            const float mn0 = fmaxf(mrow[mt][0], mx0);
            const float mn1 = fmaxf(mrow[mt][1], mx1);
            const float corr0 = __expf(mrow[mt][0] - mn0);
            const float corr1 = __expf(mrow[mt][1] - mn1);
            mrow[mt][0] = mn0; mrow[mt][1] = mn1;

            float ls0 = 0.f, ls1 = 0.f;
            #pragma unroll
            for (int nt = 0; nt < 8; nt++) {
                float p00 = __expf(s[mt][nt][0] - mn0);
                float p01 = __expf(s[mt][nt][1] - mn0);
                float p10 = __expf(s[mt][nt][2] - mn1);
                float p11 = __expf(s[mt][nt][3] - mn1);
                ls0 += p00 + p01;
                ls1 += p10 + p11;
                uint32_t* pw = Pw + (mt * 16 + ar) * PS + nt * 8 + 2 * ac;
                pw[0]          = f2tf32(p00);
                pw[1]          = f2tf32(p01);
                pw[8 * PS]     = f2tf32(p10);
                pw[8 * PS + 1] = f2tf32(p11);
            }
            ls0 += __shfl_xor_sync(0xffffffff, ls0, 1);
            ls0 += __shfl_xor_sync(0xffffffff, ls0, 2);
            ls1 += __shfl_xor_sync(0xffffffff, ls1, 1);
            ls1 += __shfl_xor_sync(0xffffffff, ls1, 2);
            lrow[mt][0] = lrow[mt][0] * corr0 + ls0;
            lrow[mt][1] = lrow[mt][1] * corr1 + ls1;

            #pragma unroll
            for (int nt = 0; nt < 8; nt++) {
                accO[mt][nt][0] *= corr0; accO[mt][nt][1] *= corr0;
                accO[mt][nt][2] *= corr1; accO[mt][nt][3] *= corr1;
            }
        }
        __syncwarp();

        // ---- O += P V  (per warp: 32 x 64, k = 64 keys) ----
        #pragma unroll
        for (int k8 = 0; k8 < 8; k8++) {
            const int k = k8 * 8;
            uint32_t a[2][4];
            #pragma unroll
            for (int mt = 0; mt < 2; mt++) {
                const int lo = mt * 16;
                a[mt][0] = Pw[(lo + ar    ) * PS + k + ac];
                a[mt][1] = Pw[(lo + ar + 8) * PS + k + ac];
                a[mt][2] = Pw[(lo + ar    ) * PS + k + ac + 4];
                a[mt][3] = Pw[(lo + ar + 8) * PS + k + ac + 4];
            }
            #pragma unroll
            for (int nt = 0; nt < 8; nt++) {
                const int n = nt * 8;
                uint32_t b0 = Vsm[(k + ac    ) * VS + n + ar];
                uint32_t b1 = Vsm[(k + ac + 4) * VS + n + ar];
                #pragma unroll
                for (int mt = 0; mt < 2; mt++) {
                    asm volatile(
                        "mma.sync.aligned.m16n8k8.row.col.f32.tf32.tf32.f32 "
                        "{%0,%1,%2,%3}, {%4,%5,%6,%7}, {%8,%9}, {%0,%1,%2,%3};\n"
                        : "+f"(accO[mt][nt][0]), "+f"(accO[mt][nt][1]),
                          "+f"(accO[mt][nt][2]), "+f"(accO[mt][nt][3])
                        : "r"(a[mt][0]), "r"(a[mt][1]), "r"(a[mt][2]), "r"(a[mt][3]),
                          "r"(b0), "r"(b1));
                }
            }
        }
    }

    // ---- normalize + store ----
    #pragma unroll
    for (int mt = 0; mt < 2; mt++) {
        const float inv0 = 1.f / lrow[mt][0];
        const float inv1 = 1.f / lrow[mt][1];
        const int r0 = q0 + warp * 32 + mt * 16 + ar;
        float* og = g_ctx + ((size_t)(b * Tt)) * Dm + h * Dh;
        #pragma unroll
        for (int nt = 0; nt < 8; nt++) {
            const int col = nt * 8 + 2 * ac;
            *(float2*)(og + (size_t)r0 * Dm + col) =
                make_float2(accO[mt][nt][0] * inv0, accO[mt][nt][1] * inv0);
            *(float2*)(og + (size_t)(r0 + 8) * Dm + col) =
                make_float2(accO[mt][nt][2] * inv1, accO[mt][nt][3] * inv1);
        }
    }
}

// ======================= launch =======================
extern "C" void kernel_launch(void* const* d_in, const int* in_sizes, int n_in,
                              void* d_out, int out_size)
{
    const float* x  = (const float*)d_in[0];
    const float* Wq = (const float*)d_in[1];
    const float* Wk = (const float*)d_in[2];
    const float* Wv = (const float*)d_in[3];
    const float* Wo = (const float*)d_in[4];
    float* out = (float*)d_out;

    cudaFuncSetAttribute(attn_mma, cudaFuncAttributeMaxDynamicSharedMemorySize,
                         ATTN_SMEM_BYTES);

    dim3 gQKV(Dm / BN, Mrows / BM, 3);
    gemm_qkv<<<gQKV, 256>>>(x, Wq, Wk, Wv);

    dim3 gA(Tt / 128, Hh, Bz);
    attn_mma<<<gA, 128, ATTN_SMEM_BYTES>>>();

    dim3 gO(Dm / BN, Mrows / BM, 1);
    gemm_out<<<gO, 256>>>(Wo, out);
}